// round 3
// baseline (speedup 1.0000x reference)
#include <cuda_runtime.h>
#include <cuda_bf16.h>
#include <math_constants.h>

// Problem constants
#define NPTS   32768      // B*H*W = 32*32*32
#define DIM    256        // channels
#define NCODE  8192       // codebook entries
#define HWSZ   1024       // H*W
#define ZQ_ELEMS (32*256*32*32)   // 8388608

// Tiling
#define BM 128            // points per block
#define BN 256            // codes per tile
#define BK 16             // d-chunk
#define TM 8              // points per thread
#define TNP 8             // code *pairs* per thread (16 codes)
#define ZSS 128           // zs row stride (floats)
#define ESS 260           // es row stride (floats), padded vs 256

#define SMEM_BYTES ((DIM*ZSS + 2*BK*ESS + BM + BM) * 4)

__device__ float g_enorm[NCODE];
__device__ int   g_best_idx[NPTS];

// ---------------- f32x2 helpers (Blackwell packed fp32) ----------------
__device__ __forceinline__ unsigned long long ffma2(unsigned long long a,
                                                    unsigned long long b,
                                                    unsigned long long c) {
    unsigned long long d;
    asm("fma.rn.f32x2 %0, %1, %2, %3;" : "=l"(d) : "l"(a), "l"(b), "l"(c));
    return d;
}
__device__ __forceinline__ unsigned long long dup2(float x) {
    unsigned long long r;
    asm("mov.b64 %0, {%1, %1};" : "=l"(r) : "f"(x));
    return r;
}
__device__ __forceinline__ void unpack2(unsigned long long v, float& lo, float& hi) {
    asm("mov.b64 {%0, %1}, %2;" : "=f"(lo), "=f"(hi) : "l"(v));
}

// ---------------- Kernel 0: codebook row norms ----------------
__global__ void k_enorm(const float* __restrict__ emb) {
    int warp = (blockIdx.x * blockDim.x + threadIdx.x) >> 5;
    int lane = threadIdx.x & 31;
    if (warp >= NCODE) return;
    const float4* r = reinterpret_cast<const float4*>(emb + (size_t)warp * DIM);
    float4 a = r[lane];
    float4 b = r[lane + 32];
    float s = a.x*a.x + a.y*a.y + a.z*a.z + a.w*a.w
            + b.x*b.x + b.y*b.y + b.z*b.z + b.w*b.w;
    #pragma unroll
    for (int off = 16; off > 0; off >>= 1)
        s += __shfl_xor_sync(0xffffffffu, s, off);
    if (lane == 0) g_enorm[warp] = s;
}

// ---------------- Kernel 1: GEMM + argmin ----------------
__global__ void __launch_bounds__(256, 1)
k_argmin(const float* __restrict__ z, const float* __restrict__ emb) {
    extern __shared__ float smem[];
    float* zs    = smem;                      // [DIM][ZSS]
    float* es    = smem + DIM * ZSS;          // [2][BK][ESS]
    float* bdist = es + 2 * BK * ESS;         // [BM]
    int*   bidx  = reinterpret_cast<int*>(bdist + BM);  // [BM]

    const int t  = threadIdx.x;
    const int tx = t & 15;          // code group (16 codes each)
    const int ty = t >> 4;          // point group (8 points each)

    const int n0  = blockIdx.x * BM;
    const int b   = n0 >> 10;
    const int hw0 = n0 & 1023;
    const float* zbase = z + ((size_t)b * DIM) * HWSZ + hw0;

    // Load this block's z tile once: zs[c][p] = z[b, c, hw0+p]
    #pragma unroll
    for (int i = t; i < DIM * (BM / 4); i += 256) {
        int c  = i >> 5;          // BM/4 = 32 float4 groups per row
        int pg = i & 31;
        float4 v = *reinterpret_cast<const float4*>(zbase + (size_t)c * HWSZ + pg * 4);
        *reinterpret_cast<float4*>(&zs[c * ZSS + pg * 4]) = v;
    }
    if (t < BM) { bdist[t] = CUDART_INF_F; bidx[t] = 0; }
    __syncthreads();

    unsigned long long acc[TM][TNP];
    float4 stage[4];

    for (int kt = 0; kt < NCODE; kt += BN) {
        #pragma unroll
        for (int p = 0; p < TM; ++p)
            #pragma unroll
            for (int u = 0; u < TNP; ++u)
                acc[p][u] = 0ull;

        const float* ebase = emb + (size_t)kt * DIM;

        // Prefetch chunk 0: chunk covers d-cols [ch*BK, ch*BK+16)
        #pragma unroll
        for (int i = 0; i < 4; ++i) {
            int s = t + i * 256;
            int code = s >> 2, cg = s & 3;
            stage[i] = *reinterpret_cast<const float4*>(
                ebase + (size_t)code * DIM + 0 * BK + cg * 4);
        }

        for (int ch = 0; ch < DIM / BK; ++ch) {
            float* eb = es + (ch & 1) * BK * ESS;
            // Commit staged chunk to smem (transposed: eb[c_local][code])
            #pragma unroll
            for (int i = 0; i < 4; ++i) {
                int s = t + i * 256;
                int code = s >> 2, cg = s & 3;
                eb[(cg * 4 + 0) * ESS + code] = stage[i].x;
                eb[(cg * 4 + 1) * ESS + code] = stage[i].y;
                eb[(cg * 4 + 2) * ESS + code] = stage[i].z;
                eb[(cg * 4 + 3) * ESS + code] = stage[i].w;
            }
            __syncthreads();
            if (ch < DIM / BK - 1) {
                int c0 = (ch + 1) * BK;
                #pragma unroll
                for (int i = 0; i < 4; ++i) {
                    int s = t + i * 256;
                    int code = s >> 2, cg = s & 3;
                    stage[i] = *reinterpret_cast<const float4*>(
                        ebase + (size_t)code * DIM + c0 + cg * 4);
                }
            }
            // Compute BK d-steps
            #pragma unroll
            for (int s = 0; s < BK; ++s) {
                int c = ch * BK + s;
                float4 za = *reinterpret_cast<const float4*>(&zs[c * ZSS + ty * TM]);
                float4 zb = *reinterpret_cast<const float4*>(&zs[c * ZSS + ty * TM + 4]);
                unsigned long long z2[TM];
                z2[0] = dup2(za.x); z2[1] = dup2(za.y);
                z2[2] = dup2(za.z); z2[3] = dup2(za.w);
                z2[4] = dup2(zb.x); z2[5] = dup2(zb.y);
                z2[6] = dup2(zb.z); z2[7] = dup2(zb.w);
                const ulonglong2* ep =
                    reinterpret_cast<const ulonglong2*>(&eb[s * ESS + tx * 16]);
                ulonglong2 e0 = ep[0], e1 = ep[1], e2 = ep[2], e3 = ep[3];
                unsigned long long ee[TNP] = {e0.x, e0.y, e1.x, e1.y,
                                              e2.x, e2.y, e3.x, e3.y};
                #pragma unroll
                for (int p = 0; p < TM; ++p)
                    #pragma unroll
                    for (int u = 0; u < TNP; ++u)
                        acc[p][u] = ffma2(z2[p], ee[u], acc[p][u]);
            }
            __syncthreads();
        }

        // Epilogue: dist = enorm[k] - 2*dot ; argmin with lowest-index tie-break
        float en[16];
        {
            const float4* e4 = reinterpret_cast<const float4*>(g_enorm + kt + tx * 16);
            float4 a = e4[0], bb = e4[1], cc = e4[2], dd = e4[3];
            en[0]=a.x; en[1]=a.y; en[2]=a.z; en[3]=a.w;
            en[4]=bb.x; en[5]=bb.y; en[6]=bb.z; en[7]=bb.w;
            en[8]=cc.x; en[9]=cc.y; en[10]=cc.z; en[11]=cc.w;
            en[12]=dd.x; en[13]=dd.y; en[14]=dd.z; en[15]=dd.w;
        }
        int kbase = kt + tx * 16;
        #pragma unroll
        for (int p = 0; p < TM; ++p) {
            float bd = CUDART_INF_F;
            int bk = 0x7fffffff;
            #pragma unroll
            for (int u = 0; u < TNP; ++u) {
                float lo, hi;
                unpack2(acc[p][u], lo, hi);
                float d0 = fmaf(-2.0f, lo, en[2 * u]);
                float d1 = fmaf(-2.0f, hi, en[2 * u + 1]);
                if (d0 < bd) { bd = d0; bk = kbase + 2 * u; }
                if (d1 < bd) { bd = d1; bk = kbase + 2 * u + 1; }
            }
            #pragma unroll
            for (int off = 8; off > 0; off >>= 1) {
                float od = __shfl_xor_sync(0xffffffffu, bd, off);
                int   ok = __shfl_xor_sync(0xffffffffu, bk, off);
                if (od < bd || (od == bd && ok < bk)) { bd = od; bk = ok; }
            }
            if (tx == 0) {
                int pi = ty * TM + p;
                if (bd < bdist[pi]) { bdist[pi] = bd; bidx[pi] = bk; }
            }
        }
    }
    __syncthreads();
    if (t < BM) g_best_idx[n0 + t] = bidx[t];
}

// ---------------- Kernel 2: output writer ----------------
// z_q[b,c,h,w] = z + (emb[idx,c] - z)  (replicating the straight-through fp32 math)
// Tail (if present): indices as float.
__global__ void k_write(const float* __restrict__ z, const float* __restrict__ emb,
                        float* __restrict__ out, int out_size) {
    int i = blockIdx.x * 256 + threadIdx.x;
    if (i >= out_size) return;
    if (i < ZQ_ELEMS) {
        int hw = i & 1023;
        int bc = i >> 10;
        int c  = bc & 255;
        int b  = bc >> 8;
        int n  = (b << 10) + hw;
        int k  = g_best_idx[n];
        float e  = emb[(size_t)k * DIM + c];
        float zv = z[i];
        out[i] = __fadd_rn(zv, __fsub_rn(e, zv));
    } else {
        int j = i - ZQ_ELEMS;
        out[i] = (j < NPTS) ? (float)g_best_idx[j] : 0.0f;
    }
}

extern "C" void kernel_launch(void* const* d_in, const int* in_sizes, int n_in,
                              void* d_out, int out_size) {
    // Disambiguate input order by size (z has 8388608 elems, embedding 2097152)
    const float* z   = (const float*)d_in[0];
    const float* emb = (const float*)d_in[1];
    if (in_sizes[0] != ZQ_ELEMS) {
        const float* tmp = z; z = emb; emb = tmp;
    }
    float* out = (float*)d_out;

    cudaFuncSetAttribute(k_argmin, cudaFuncAttributeMaxDynamicSharedMemorySize,
                         SMEM_BYTES);

    k_enorm<<<NCODE / 8, 256>>>(emb);
    k_argmin<<<NPTS / BM, 256, SMEM_BYTES>>>(z, emb);
    int wgrid = (out_size + 255) / 256;
    k_write<<<wgrid, 256>>>(z, emb, out, out_size);
}

// round 4
// speedup vs baseline: 1.6010x; 1.6010x over previous
#include <cuda_runtime.h>
#include <cuda_bf16.h>
#include <math_constants.h>

// Problem constants
#define NPTS   32768      // B*H*W = 32*32*32
#define DIM    256        // channels
#define NCODE  8192       // codebook entries
#define HWSZ   1024       // H*W
#define ZQ_ELEMS (32*256*32*32)   // 8388608

// Tiling
#define BM 128            // points per block
#define BN 256            // codes per tile
#define BK 16             // d-chunk
#define TM 8              // points per thread
#define TNP 8             // code *pairs* per thread (16 codes, interleaved)
#define ZSS 128           // zs row stride (floats)
#define ESS 260           // es row stride (floats), padded vs 256

#define SMEM_BYTES ((DIM*ZSS + 2*BK*ESS + BM + BM) * 4)

__device__ float g_enorm[NCODE];
__device__ int   g_best_idx[NPTS];

// ---------------- f32x2 helpers (Blackwell packed fp32) ----------------
__device__ __forceinline__ unsigned long long ffma2(unsigned long long a,
                                                    unsigned long long b,
                                                    unsigned long long c) {
    unsigned long long d;
    asm("fma.rn.f32x2 %0, %1, %2, %3;" : "=l"(d) : "l"(a), "l"(b), "l"(c));
    return d;
}
__device__ __forceinline__ unsigned long long dup2(float x) {
    unsigned long long r;
    asm("mov.b64 %0, {%1, %1};" : "=l"(r) : "f"(x));
    return r;
}
__device__ __forceinline__ void unpack2(unsigned long long v, float& lo, float& hi) {
    asm("mov.b64 {%0, %1}, %2;" : "=f"(lo), "=f"(hi) : "l"(v));
}

// ---------------- Kernel 0: codebook row norms ----------------
__global__ void k_enorm(const float* __restrict__ emb) {
    int warp = (blockIdx.x * blockDim.x + threadIdx.x) >> 5;
    int lane = threadIdx.x & 31;
    if (warp >= NCODE) return;
    const float4* r = reinterpret_cast<const float4*>(emb + (size_t)warp * DIM);
    float4 a = r[lane];
    float4 b = r[lane + 32];
    float s = a.x*a.x + a.y*a.y + a.z*a.z + a.w*a.w
            + b.x*b.x + b.y*b.y + b.z*b.z + b.w*b.w;
    #pragma unroll
    for (int off = 16; off > 0; off >>= 1)
        s += __shfl_xor_sync(0xffffffffu, s, off);
    if (lane == 0) g_enorm[warp] = s;
}

// ---------------- Kernel 1: GEMM + argmin ----------------
__global__ void __launch_bounds__(256, 1)
k_argmin(const float* __restrict__ z, const float* __restrict__ emb) {
    extern __shared__ float smem[];
    float* zs    = smem;                      // [DIM][ZSS]
    float* es    = smem + DIM * ZSS;          // [2][BK][ESS]
    float* bdist = es + 2 * BK * ESS;         // [BM]
    int*   bidx  = reinterpret_cast<int*>(bdist + BM);  // [BM]

    const int t  = threadIdx.x;
    const int tx = t & 15;          // code-pair lane (owns codes 2*tx+32*u, +1)
    const int ty = t >> 4;          // point group (8 points each)

    const int n0  = blockIdx.x * BM;
    const int b   = n0 >> 10;
    const int hw0 = n0 & 1023;
    const float* zbase = z + ((size_t)b * DIM) * HWSZ + hw0;

    // Load this block's z tile once: zs[c][p] = z[b, c, hw0+p]
    #pragma unroll
    for (int i = t; i < DIM * (BM / 4); i += 256) {
        int c  = i >> 5;          // BM/4 = 32 float4 groups per row
        int pg = i & 31;
        float4 v = *reinterpret_cast<const float4*>(zbase + (size_t)c * HWSZ + pg * 4);
        *reinterpret_cast<float4*>(&zs[c * ZSS + pg * 4]) = v;
    }
    if (t < BM) { bdist[t] = CUDART_INF_F; bidx[t] = 0; }
    __syncthreads();

    unsigned long long acc[TM][TNP];
    float4 stage[4];

    for (int kt = 0; kt < NCODE; kt += BN) {
        #pragma unroll
        for (int p = 0; p < TM; ++p)
            #pragma unroll
            for (int u = 0; u < TNP; ++u)
                acc[p][u] = 0ull;

        const float* ebase = emb + (size_t)kt * DIM;

        // Prefetch chunk 0: chunk covers d-cols [ch*BK, ch*BK+16)
        #pragma unroll
        for (int i = 0; i < 4; ++i) {
            int s = t + i * 256;
            int code = s >> 2, cg = s & 3;
            stage[i] = *reinterpret_cast<const float4*>(
                ebase + (size_t)code * DIM + 0 * BK + cg * 4);
        }

        for (int ch = 0; ch < DIM / BK; ++ch) {
            float* eb = es + (ch & 1) * BK * ESS;
            // Commit staged chunk to smem (transposed: eb[c_local][code])
            #pragma unroll
            for (int i = 0; i < 4; ++i) {
                int s = t + i * 256;
                int code = s >> 2, cg = s & 3;
                eb[(cg * 4 + 0) * ESS + code] = stage[i].x;
                eb[(cg * 4 + 1) * ESS + code] = stage[i].y;
                eb[(cg * 4 + 2) * ESS + code] = stage[i].z;
                eb[(cg * 4 + 3) * ESS + code] = stage[i].w;
            }
            __syncthreads();
            if (ch < DIM / BK - 1) {
                int c0 = (ch + 1) * BK;
                #pragma unroll
                for (int i = 0; i < 4; ++i) {
                    int s = t + i * 256;
                    int code = s >> 2, cg = s & 3;
                    stage[i] = *reinterpret_cast<const float4*>(
                        ebase + (size_t)code * DIM + c0 + cg * 4);
                }
            }
            // Compute BK d-steps (unroll capped to keep body in L0 I$)
            #pragma unroll 4
            for (int s = 0; s < BK; ++s) {
                int c = ch * BK + s;
                float4 za = *reinterpret_cast<const float4*>(&zs[c * ZSS + ty * TM]);
                float4 zb = *reinterpret_cast<const float4*>(&zs[c * ZSS + ty * TM + 4]);
                unsigned long long z2[TM];
                z2[0] = dup2(za.x); z2[1] = dup2(za.y);
                z2[2] = dup2(za.z); z2[3] = dup2(za.w);
                z2[4] = dup2(zb.x); z2[5] = dup2(zb.y);
                z2[6] = dup2(zb.z); z2[7] = dup2(zb.w);
                // Interleaved code-pair reads: lane tx reads codes (32u+2tx, +1).
                // Byte stride across lanes = 8 -> all 32 banks hit once: conflict-free.
                const float* erow = &eb[s * ESS + 2 * tx];
                unsigned long long ee[TNP];
                #pragma unroll
                for (int u = 0; u < TNP; ++u)
                    ee[u] = *reinterpret_cast<const unsigned long long*>(erow + 32 * u);
                #pragma unroll
                for (int p = 0; p < TM; ++p)
                    #pragma unroll
                    for (int u = 0; u < TNP; ++u)
                        acc[p][u] = ffma2(z2[p], ee[u], acc[p][u]);
            }
            __syncthreads();
        }

        // Epilogue: dist = enorm[k] - 2*dot ; argmin with lowest-index tie-break
        // Lane tx owns code pairs k = kt + 32*u + 2*tx (+1).
        float2 en2[TNP];
        #pragma unroll
        for (int u = 0; u < TNP; ++u)
            en2[u] = *reinterpret_cast<const float2*>(g_enorm + kt + 32 * u + 2 * tx);

        #pragma unroll
        for (int p = 0; p < TM; ++p) {
            float bd = CUDART_INF_F;
            int bk = 0x7fffffff;
            #pragma unroll
            for (int u = 0; u < TNP; ++u) {
                float lo, hi;
                unpack2(acc[p][u], lo, hi);
                int k0 = kt + 32 * u + 2 * tx;
                float d0 = fmaf(-2.0f, lo, en2[u].x);
                float d1 = fmaf(-2.0f, hi, en2[u].y);
                if (d0 < bd || (d0 == bd && k0 < bk))     { bd = d0; bk = k0; }
                if (d1 < bd || (d1 == bd && k0 + 1 < bk)) { bd = d1; bk = k0 + 1; }
            }
            #pragma unroll
            for (int off = 8; off > 0; off >>= 1) {
                float od = __shfl_xor_sync(0xffffffffu, bd, off);
                int   ok = __shfl_xor_sync(0xffffffffu, bk, off);
                if (od < bd || (od == bd && ok < bk)) { bd = od; bk = ok; }
            }
            if (tx == 0) {
                int pi = ty * TM + p;
                if (bd < bdist[pi] || (bd == bdist[pi] && bk < bidx[pi])) {
                    bdist[pi] = bd; bidx[pi] = bk;
                }
            }
        }
    }
    __syncthreads();
    if (t < BM) g_best_idx[n0 + t] = bidx[t];
}

// ---------------- Kernel 2: output writer ----------------
// z_q[b,c,h,w] = z + (emb[idx,c] - z)  (replicating the straight-through fp32 math)
// Tail (if present): indices as float.
__global__ void k_write(const float* __restrict__ z, const float* __restrict__ emb,
                        float* __restrict__ out, int out_size) {
    int i = blockIdx.x * 256 + threadIdx.x;
    if (i >= out_size) return;
    if (i < ZQ_ELEMS) {
        int hw = i & 1023;
        int bc = i >> 10;
        int c  = bc & 255;
        int b  = bc >> 8;
        int n  = (b << 10) + hw;
        int k  = g_best_idx[n];
        float e  = emb[(size_t)k * DIM + c];
        float zv = z[i];
        out[i] = __fadd_rn(zv, __fsub_rn(e, zv));
    } else {
        int j = i - ZQ_ELEMS;
        out[i] = (j < NPTS) ? (float)g_best_idx[j] : 0.0f;
    }
}

extern "C" void kernel_launch(void* const* d_in, const int* in_sizes, int n_in,
                              void* d_out, int out_size) {
    // Disambiguate input order by size (z has 8388608 elems, embedding 2097152)
    const float* z   = (const float*)d_in[0];
    const float* emb = (const float*)d_in[1];
    if (in_sizes[0] != ZQ_ELEMS) {
        const float* tmp = z; z = emb; emb = tmp;
    }
    float* out = (float*)d_out;

    cudaFuncSetAttribute(k_argmin, cudaFuncAttributeMaxDynamicSharedMemorySize,
                         SMEM_BYTES);

    k_enorm<<<NCODE / 8, 256>>>(emb);
    k_argmin<<<NPTS / BM, 256, SMEM_BYTES>>>(z, emb);
    int wgrid = (out_size + 255) / 256;
    k_write<<<wgrid, 256>>>(z, emb, out, out_size);
}

// round 7
// speedup vs baseline: 1.8916x; 1.1815x over previous
#include <cuda_runtime.h>
#include <cuda_bf16.h>
#include <math_constants.h>
#include <cstdint>

// Problem constants
#define NPTS   32768
#define DIM    256
#define NCODE  8192
#define HWSZ   1024
#define ZQ_ELEMS (32*256*32*32)

// Tiling
#define BM 128                 // points per CTA
#define NT 64                  // codes per tile
#define NTILES (NCODE/NT)      // 128
#define NCHUNK (NTILES*4)      // (tile,chunk) linear count: 4 k-chunks of 64 d
#define MARGIN 0.25f
#define MAXC 8

// SMEM layout (bytes)
#define SM_EB   0                  // e chunk: hi 8192 + lo 8192 = 16384
#define SM_D    16384              // D dump: 128 rows x 68 floats = 34816
#define DST     68                 // D row stride (floats)
#define SM_EN   (16384 + 34816)    // 64 floats = 256
#define SMEM_TOTAL (SM_EN + 256)

__device__ float g_enorm[NCODE];
__device__ int   g_best_idx[NPTS];
__device__ unsigned int g_flag[NPTS];
__device__ __align__(16) __nv_bfloat16 g_zhi[NPTS * DIM];
__device__ __align__(16) __nv_bfloat16 g_zlo[NPTS * DIM];
__device__ __align__(16) __nv_bfloat16 g_ehi[NCODE * DIM];
__device__ __align__(16) __nv_bfloat16 g_elo[NCODE * DIM];

// ---------------- PTX helpers (baseline ISA only, no tcgen05) ----------------
__device__ __forceinline__ uint32_t smem_u32(const void* p) {
    uint32_t a;
    asm("{ .reg .u64 t; cvta.to.shared.u64 t, %1; cvt.u32.u64 %0, t; }"
        : "=r"(a) : "l"(p));
    return a;
}

// st.shared on a shared-window u32 address (the R6 bug: these were generic stores)
__device__ __forceinline__ void sts128(uint32_t addr, uint4 v) {
    asm volatile("st.shared.v4.b32 [%0], {%1,%2,%3,%4};"
        :: "r"(addr), "r"(v.x), "r"(v.y), "r"(v.z), "r"(v.w) : "memory");
}

__device__ __forceinline__ void mma_bf16(float* c, uint32_t a0, uint32_t a1,
                                         uint32_t a2, uint32_t a3,
                                         uint32_t b0, uint32_t b1) {
    asm volatile(
        "mma.sync.aligned.m16n8k16.row.col.f32.bf16.bf16.f32 "
        "{%0,%1,%2,%3}, {%4,%5,%6,%7}, {%8,%9}, {%0,%1,%2,%3};"
        : "+f"(c[0]), "+f"(c[1]), "+f"(c[2]), "+f"(c[3])
        : "r"(a0), "r"(a1), "r"(a2), "r"(a3), "r"(b0), "r"(b1));
}

__device__ __forceinline__ void ldsm_x4(uint32_t& r0, uint32_t& r1,
                                        uint32_t& r2, uint32_t& r3,
                                        uint32_t addr) {
    asm volatile("ldmatrix.sync.aligned.m8n8.x4.shared.b16 {%0,%1,%2,%3}, [%4];"
        : "=r"(r0), "=r"(r1), "=r"(r2), "=r"(r3) : "r"(addr));
}

// ---------------- Kernel 0: codebook row norms ----------------
__global__ void k_enorm(const float* __restrict__ emb) {
    int warp = (blockIdx.x * blockDim.x + threadIdx.x) >> 5;
    int lane = threadIdx.x & 31;
    if (warp >= NCODE) return;
    const float4* r = reinterpret_cast<const float4*>(emb + (size_t)warp * DIM);
    float4 a = r[lane];
    float4 b = r[lane + 32];
    float s = a.x*a.x + a.y*a.y + a.z*a.z + a.w*a.w
            + b.x*b.x + b.y*b.y + b.z*b.z + b.w*b.w;
    #pragma unroll
    for (int off = 16; off > 0; off >>= 1)
        s += __shfl_xor_sync(0xffffffffu, s, off);
    if (lane == 0) g_enorm[warp] = s;
}

// ---------------- Kernel 0b: split e into bf16 hi/lo ----------------
__global__ void k_esplit(const float* __restrict__ emb) {
    int i = blockIdx.x * 256 + threadIdx.x;
    if (i >= NCODE * DIM) return;
    float v = emb[i];
    __nv_bfloat16 h = __float2bfloat16(v);
    g_ehi[i] = h;
    g_elo[i] = __float2bfloat16(v - __bfloat162float(h));
}

// ---------------- Kernel 0c: transpose+split z into bf16 hi/lo (n-major) ----------------
__global__ void k_zsplit(const float* __restrict__ z) {
    __shared__ float s[64][65];
    int bid = blockIdx.x;
    int b   = bid >> 6;
    int hwb = (bid >> 2) & 15;
    int cb  = bid & 3;
    int hw0 = hwb * 64, c0 = cb * 64;
    const float* zb = z + (size_t)b * DIM * HWSZ;
    int t = threadIdx.x;
    #pragma unroll
    for (int i = t; i < 4096; i += 256) {
        int c = i >> 6, hw = i & 63;
        s[hw][c] = zb[(size_t)(c0 + c) * HWSZ + hw0 + hw];
    }
    __syncthreads();
    int n0 = b * HWSZ + hw0;
    #pragma unroll
    for (int i = t; i < 4096; i += 256) {
        int hw = i >> 6, c = i & 63;
        float v = s[hw][c];
        __nv_bfloat16 h = __float2bfloat16(v);
        __nv_bfloat16 l = __float2bfloat16(v - __bfloat162float(h));
        size_t o = (size_t)(n0 + hw) * DIM + c0 + c;
        g_zhi[o] = h;
        g_zlo[o] = l;
    }
}

// ---------------- Kernel 1: HMMA split-GEMM + margin argmin + exact rescore ----------------
__global__ void __launch_bounds__(256, 1)
k_vq(const float* __restrict__ z, const float* __restrict__ emb) {
    extern __shared__ char smem[];
    const uint32_t sb = smem_u32(smem);
    const int tid  = threadIdx.x;
    const int w    = tid >> 5;
    const int lane = tid & 31;
    const int q    = lane >> 2;        // group id 0..7
    const int e    = lane & 3;         // thread-in-group
    const int n0   = blockIdx.x * BM;

    // ---- Resident A fragments: z hi/lo for this warp's 16 rows, all K=256 ----
    // m16n8k16 A mapping: a0=A[q][2e..], a1=A[q+8][..], a2=A[q][2e+8..], a3=A[q+8][2e+8..]
    uint32_t Ah[64], Al[64];
    {
        const __nv_bfloat16* zh1 = g_zhi + (size_t)(n0 + w * 16 + q) * DIM;
        const __nv_bfloat16* zh2 = zh1 + 8 * DIM;
        const __nv_bfloat16* zl1 = g_zlo + (size_t)(n0 + w * 16 + q) * DIM;
        const __nv_bfloat16* zl2 = zl1 + 8 * DIM;
        #pragma unroll
        for (int ks = 0; ks < 16; ++ks) {
            int c0 = ks * 16 + 2 * e;
            Ah[ks*4+0] = *reinterpret_cast<const uint32_t*>(zh1 + c0);
            Ah[ks*4+1] = *reinterpret_cast<const uint32_t*>(zh2 + c0);
            Ah[ks*4+2] = *reinterpret_cast<const uint32_t*>(zh1 + c0 + 8);
            Ah[ks*4+3] = *reinterpret_cast<const uint32_t*>(zh2 + c0 + 8);
            Al[ks*4+0] = *reinterpret_cast<const uint32_t*>(zl1 + c0);
            Al[ks*4+1] = *reinterpret_cast<const uint32_t*>(zl2 + c0);
            Al[ks*4+2] = *reinterpret_cast<const uint32_t*>(zl1 + c0 + 8);
            Al[ks*4+3] = *reinterpret_cast<const uint32_t*>(zl2 + c0 + 8);
        }
    }

    // ---- B ldmatrix lane constants (e chunk in SMEM, XOR-swizzled 128B rows) ----
    const int nl  = (lane & 7) | ((lane >> 4) << 3);  // row 0..15 within 16-row pair
    const int h   = (lane >> 3) & 1;                  // k-half selector
    const int nl7 = nl & 7;
    const uint32_t eb_lane = sb + SM_EB + nl * 128;

    // ---- staging lane mapping: 4 threads per code row, 2x16B each per split ----
    const int srow = tid >> 2, scp = tid & 3;
    const uint32_t st0 = sb + SM_EB + srow * 128 + (uint32_t)(((scp    ) ^ (srow & 7)) << 4);
    const uint32_t st1 = sb + SM_EB + srow * 128 + (uint32_t)(((scp + 4) ^ (srow & 7)) << 4);

    uint4 sh0, sh1, sl0, sl1;
    auto stage = [&](int c) {
        int ktn = (c >> 2) * NT, dcn = c & 3;
        const __nv_bfloat16* gh = g_ehi + (size_t)(ktn + srow) * DIM + dcn * 64;
        const __nv_bfloat16* gl = g_elo + (size_t)(ktn + srow) * DIM + dcn * 64;
        sh0 = *reinterpret_cast<const uint4*>(gh + scp * 8);
        sh1 = *reinterpret_cast<const uint4*>(gh + scp * 8 + 32);
        sl0 = *reinterpret_cast<const uint4*>(gl + scp * 8);
        sl1 = *reinterpret_cast<const uint4*>(gl + scp * 8 + 32);
    };
    stage(0);

    float acc[32];
    float bd = CUDART_INF_F; int bk = 0x7fffffff;
    float cd[MAXC]; int ck[MAXC]; int m = 0; int ovf = 0;
    float* Ds   = reinterpret_cast<float*>(smem + SM_D);
    float* en_s = reinterpret_cast<float*>(smem + SM_EN);

    #pragma unroll 1
    for (int t1 = 0; t1 < NTILES; ++t1) {
        #pragma unroll 1
        for (int dc = 0; dc < 4; ++dc) {
            __syncthreads();   // prior compute / scan done
            sts128(st0, sh0);
            sts128(st1, sh1);
            sts128(st0 + 8192, sl0);
            sts128(st1 + 8192, sl1);
            __syncthreads();
            int cn = t1 * 4 + dc + 1;
            if (cn < NCHUNK) stage(cn);   // LDG in flight behind compute

            if (dc == 0) {
                #pragma unroll
                for (int i = 0; i < 32; ++i) acc[i] = 0.f;
            }
            #pragma unroll
            for (int ks = 0; ks < 4; ++ks) {
                int gks = dc * 4 + ks;
                uint32_t a0 = Ah[gks*4+0], a1 = Ah[gks*4+1],
                         a2 = Ah[gks*4+2], a3 = Ah[gks*4+3];
                uint32_t l0 = Al[gks*4+0], l1 = Al[gks*4+1],
                         l2 = Al[gks*4+2], l3 = Al[gks*4+3];
                uint32_t koff = (uint32_t)(((ks * 2 + h) ^ nl7) << 4);
                #pragma unroll
                for (int jj = 0; jj < 4; ++jj) {
                    uint32_t ba = eb_lane + jj * 2048 + koff;
                    uint32_t bh0, bh1, bh2, bh3, bl0, bl1, bl2, bl3;
                    ldsm_x4(bh0, bh1, bh2, bh3, ba);
                    ldsm_x4(bl0, bl1, bl2, bl3, ba + 8192);
                    float* c0 = acc + (2*jj) * 4;
                    float* c1 = acc + (2*jj + 1) * 4;
                    mma_bf16(c0, a0, a1, a2, a3, bh0, bh1);
                    mma_bf16(c1, a0, a1, a2, a3, bh2, bh3);
                    mma_bf16(c0, a0, a1, a2, a3, bl0, bl1);
                    mma_bf16(c1, a0, a1, a2, a3, bl2, bl3);
                    mma_bf16(c0, l0, l1, l2, l3, bh0, bh1);
                    mma_bf16(c1, l0, l1, l2, l3, bh2, bh3);
                }
            }
        }

        // ---- dump D tile (m16n8 C mapping) ----
        {
            int r1 = w * 16 + q, r2 = r1 + 8;
            #pragma unroll
            for (int j = 0; j < 8; ++j) {
                *reinterpret_cast<float2*>(&Ds[r1 * DST + j * 8 + 2 * e]) =
                    make_float2(acc[j*4+0], acc[j*4+1]);
                *reinterpret_cast<float2*>(&Ds[r2 * DST + j * 8 + 2 * e]) =
                    make_float2(acc[j*4+2], acc[j*4+3]);
            }
        }
        if (tid < NT) en_s[tid] = g_enorm[t1 * NT + tid];
        __syncthreads();

        // ---- per-point scan (thread p = point), staggered for bank-freedom ----
        if (tid < BM) {
            int kt = t1 * NT;
            const float* row = Ds + tid * DST;
            #pragma unroll 4
            for (int i = 0; i < NT; ++i) {
                int c = (tid + i) & (NT - 1);
                float dap = fmaf(-2.0f, row[c], en_s[c]);
                if (dap < bd + MARGIN) {
                    int k = kt + c;
                    float iv; int ik;
                    if (dap < bd) { iv = bd; ik = bk; bd = dap; bk = k; }
                    else          { iv = dap; ik = k; }
                    if (ik != 0x7fffffff) {
                        if (m == MAXC) {
                            int wv = 0;
                            for (int qq = 0; qq < MAXC; ++qq)
                                if (cd[qq] < bd + MARGIN) { cd[wv] = cd[qq]; ck[wv] = ck[qq]; ++wv; }
                            m = wv;
                        }
                        if (m < MAXC) { cd[m] = iv; ck[m] = ik; ++m; }
                        else ovf = 1;
                    }
                }
            }
        }
    }

    // ---- exact fp32 rescore of candidate set ----
    if (tid < BM) {
        int n = n0 + tid;
        const float* zr = z + (size_t)(n >> 10) * (DIM * HWSZ) + (n & 1023);
        float bestd = CUDART_INF_F; int bestk = 0x7fffffff;
        for (int ci = -1; ci < m; ++ci) {
            int k;
            if (ci < 0) k = bk;
            else {
                if (!(cd[ci] < bd + MARGIN)) continue;
                k = ck[ci];
                if (k == bk) continue;
            }
            const float* er = emb + (size_t)k * DIM;
            float dot = 0.f;
            #pragma unroll 8
            for (int c = 0; c < DIM; ++c)
                dot = fmaf(zr[(size_t)c * HWSZ], er[c], dot);
            float dd = fmaf(-2.0f, dot, g_enorm[k]);
            if (dd < bestd || (dd == bestd && k < bestk)) { bestd = dd; bestk = k; }
        }
        g_best_idx[n] = bestk;
        g_flag[n] = (unsigned)ovf;
    }
}

// ---------------- Kernel 1b: exact full-scan fallback for overflowed points ----------------
__global__ void k_fb(const float* __restrict__ z, const float* __restrict__ emb) {
    int w = (blockIdx.x * blockDim.x + threadIdx.x) >> 5;
    int lane = threadIdx.x & 31;
    if (w >= NPTS) return;
    if (g_flag[w] == 0) return;
    const float* zr = z + (size_t)(w >> 10) * (DIM * HWSZ) + (w & 1023);
    float bd = CUDART_INF_F; int bk = 0x7fffffff;
    for (int k = lane; k < NCODE; k += 32) {
        const float* er = emb + (size_t)k * DIM;
        float dot = 0.f;
        #pragma unroll 8
        for (int c = 0; c < DIM; ++c)
            dot = fmaf(zr[(size_t)c * HWSZ], er[c], dot);
        float dd = fmaf(-2.0f, dot, g_enorm[k]);
        if (dd < bd || (dd == bd && k < bk)) { bd = dd; bk = k; }
    }
    #pragma unroll
    for (int off = 16; off > 0; off >>= 1) {
        float od = __shfl_xor_sync(0xffffffffu, bd, off);
        int   ok = __shfl_xor_sync(0xffffffffu, bk, off);
        if (od < bd || (od == bd && ok < bk)) { bd = od; bk = ok; }
    }
    if (lane == 0) g_best_idx[w] = bk;
}

// ---------------- Kernel 2: output writer ----------------
__global__ void k_write(const float* __restrict__ z, const float* __restrict__ emb,
                        float* __restrict__ out, int out_size) {
    int i = blockIdx.x * 256 + threadIdx.x;
    if (i >= out_size) return;
    if (i < ZQ_ELEMS) {
        int hw = i & 1023;
        int bc = i >> 10;
        int c  = bc & 255;
        int b  = bc >> 8;
        int n  = (b << 10) + hw;
        int k  = g_best_idx[n];
        float ev = emb[(size_t)k * DIM + c];
        float zv = z[i];
        out[i] = __fadd_rn(zv, __fsub_rn(ev, zv));
    } else {
        int j = i - ZQ_ELEMS;
        out[i] = (j < NPTS) ? (float)g_best_idx[j] : 0.0f;
    }
}

extern "C" void kernel_launch(void* const* d_in, const int* in_sizes, int n_in,
                              void* d_out, int out_size) {
    const float* z   = (const float*)d_in[0];
    const float* emb = (const float*)d_in[1];
    if (in_sizes[0] != ZQ_ELEMS) {
        const float* tmp = z; z = emb; emb = tmp;
    }
    float* out = (float*)d_out;

    cudaFuncSetAttribute(k_vq, cudaFuncAttributeMaxDynamicSharedMemorySize,
                         SMEM_TOTAL);

    k_enorm<<<NCODE / 8, 256>>>(emb);
    k_esplit<<<(NCODE * DIM) / 256, 256>>>(emb);
    k_zsplit<<<2048, 256>>>(z);
    k_vq<<<NPTS / BM, 256, SMEM_TOTAL>>>(z, emb);
    k_fb<<<NPTS / 8, 256>>>(z, emb);
    int wgrid = (out_size + 255) / 256;
    k_write<<<wgrid, 256>>>(z, emb, out, out_size);
}

// round 8
// speedup vs baseline: 2.4237x; 1.2813x over previous
#include <cuda_runtime.h>
#include <cuda_bf16.h>
#include <math_constants.h>
#include <cstdint>

// Problem constants
#define NPTS   32768
#define DIM    256
#define NCODE  8192
#define HWSZ   1024
#define ZQ_ELEMS (32*256*32*32)

// Tiling
#define BM 128                 // points per CTA
#define NT 64                  // codes per tile
#define NTILES (NCODE/NT)      // 128
#define MARGIN 0.25f
#define MAXC 8

// SMEM layout (bytes)
// e tile (full 256-d, hi+lo), double buffered: 2 x 65536
//   within buffer: split(2) x chunk(4) x [64 rows x 128B, XOR-swizzled]
#define SM_EB   0
#define SM_D    131072             // D dump: 2 k-half planes x 128 rows x 68 floats
#define DST     68
#define SM_EN   (131072 + 69632)   // 64 floats
#define SMEM_TOTAL (SM_EN + 256)

__device__ float g_enorm[NCODE];
__device__ int   g_best_idx[NPTS];
__device__ unsigned int g_flag[NPTS];
__device__ __align__(16) __nv_bfloat16 g_zhi[NPTS * DIM];
__device__ __align__(16) __nv_bfloat16 g_zlo[NPTS * DIM];
__device__ __align__(16) __nv_bfloat16 g_ehi[NCODE * DIM];
__device__ __align__(16) __nv_bfloat16 g_elo[NCODE * DIM];

// ---------------- PTX helpers (baseline ISA only) ----------------
__device__ __forceinline__ uint32_t smem_u32(const void* p) {
    uint32_t a;
    asm("{ .reg .u64 t; cvta.to.shared.u64 t, %1; cvt.u32.u64 %0, t; }"
        : "=r"(a) : "l"(p));
    return a;
}

__device__ __forceinline__ void cp_async16(uint32_t dst, const void* src) {
    asm volatile("cp.async.cg.shared.global [%0], [%1], 16;"
        :: "r"(dst), "l"(src) : "memory");
}
#define CP_COMMIT() asm volatile("cp.async.commit_group;" ::: "memory")
#define CP_WAIT1()  asm volatile("cp.async.wait_group 1;" ::: "memory")
#define CP_WAIT0()  asm volatile("cp.async.wait_group 0;" ::: "memory")

__device__ __forceinline__ void mma_bf16(float* c, uint32_t a0, uint32_t a1,
                                         uint32_t a2, uint32_t a3,
                                         uint32_t b0, uint32_t b1) {
    asm volatile(
        "mma.sync.aligned.m16n8k16.row.col.f32.bf16.bf16.f32 "
        "{%0,%1,%2,%3}, {%4,%5,%6,%7}, {%8,%9}, {%0,%1,%2,%3};"
        : "+f"(c[0]), "+f"(c[1]), "+f"(c[2]), "+f"(c[3])
        : "r"(a0), "r"(a1), "r"(a2), "r"(a3), "r"(b0), "r"(b1));
}

__device__ __forceinline__ void ldsm_x4(uint32_t& r0, uint32_t& r1,
                                        uint32_t& r2, uint32_t& r3,
                                        uint32_t addr) {
    asm volatile("ldmatrix.sync.aligned.m8n8.x4.shared.b16 {%0,%1,%2,%3}, [%4];"
        : "=r"(r0), "=r"(r1), "=r"(r2), "=r"(r3) : "r"(addr));
}

// ---------------- Kernel 0: codebook row norms ----------------
__global__ void k_enorm(const float* __restrict__ emb) {
    int warp = (blockIdx.x * blockDim.x + threadIdx.x) >> 5;
    int lane = threadIdx.x & 31;
    if (warp >= NCODE) return;
    const float4* r = reinterpret_cast<const float4*>(emb + (size_t)warp * DIM);
    float4 a = r[lane];
    float4 b = r[lane + 32];
    float s = a.x*a.x + a.y*a.y + a.z*a.z + a.w*a.w
            + b.x*b.x + b.y*b.y + b.z*b.z + b.w*b.w;
    #pragma unroll
    for (int off = 16; off > 0; off >>= 1)
        s += __shfl_xor_sync(0xffffffffu, s, off);
    if (lane == 0) g_enorm[warp] = s;
}

// ---------------- Kernel 0b: split e into bf16 hi/lo ----------------
__global__ void k_esplit(const float* __restrict__ emb) {
    int i = blockIdx.x * 256 + threadIdx.x;
    if (i >= NCODE * DIM) return;
    float v = emb[i];
    __nv_bfloat16 h = __float2bfloat16(v);
    g_ehi[i] = h;
    g_elo[i] = __float2bfloat16(v - __bfloat162float(h));
}

// ---------------- Kernel 0c: transpose+split z into bf16 hi/lo (n-major) ----------------
__global__ void k_zsplit(const float* __restrict__ z) {
    __shared__ float s[64][65];
    int bid = blockIdx.x;
    int b   = bid >> 6;
    int hwb = (bid >> 2) & 15;
    int cb  = bid & 3;
    int hw0 = hwb * 64, c0 = cb * 64;
    const float* zb = z + (size_t)b * DIM * HWSZ;
    int t = threadIdx.x;
    #pragma unroll
    for (int i = t; i < 4096; i += 256) {
        int c = i >> 6, hw = i & 63;
        s[hw][c] = zb[(size_t)(c0 + c) * HWSZ + hw0 + hw];
    }
    __syncthreads();
    int n0 = b * HWSZ + hw0;
    #pragma unroll
    for (int i = t; i < 4096; i += 256) {
        int hw = i >> 6, c = i & 63;
        float v = s[hw][c];
        __nv_bfloat16 h = __float2bfloat16(v);
        __nv_bfloat16 l = __float2bfloat16(v - __bfloat162float(h));
        size_t o = (size_t)(n0 + hw) * DIM + c0 + c;
        g_zhi[o] = h;
        g_zlo[o] = l;
    }
}

// ---------------- Kernel 1: HMMA split-GEMM, 16 warps, k-split, cp.async ----------------
__global__ void __launch_bounds__(512, 1)
k_vq(const float* __restrict__ z, const float* __restrict__ emb) {
    extern __shared__ char smem[];
    const uint32_t sb = smem_u32(smem);
    const int tid   = threadIdx.x;
    const int w     = tid >> 5;
    const int lane  = tid & 31;
    const int mgrp  = w >> 1;          // 0..7: which 16 point-rows
    const int khalf = w & 1;           // 0..1: which 128-d half
    const int q     = lane >> 2;
    const int e     = lane & 3;
    const int n0    = blockIdx.x * BM;

    // ---- Resident A fragments: 16 rows x 128 dims (this warp's k-half), hi+lo ----
    uint32_t Ah[32], Al[32];
    {
        const __nv_bfloat16* zh1 = g_zhi + (size_t)(n0 + mgrp * 16 + q) * DIM + khalf * 128;
        const __nv_bfloat16* zh2 = zh1 + 8 * DIM;
        const __nv_bfloat16* zl1 = g_zlo + (size_t)(n0 + mgrp * 16 + q) * DIM + khalf * 128;
        const __nv_bfloat16* zl2 = zl1 + 8 * DIM;
        #pragma unroll
        for (int ks = 0; ks < 8; ++ks) {
            int c0 = ks * 16 + 2 * e;
            Ah[ks*4+0] = *reinterpret_cast<const uint32_t*>(zh1 + c0);
            Ah[ks*4+1] = *reinterpret_cast<const uint32_t*>(zh2 + c0);
            Ah[ks*4+2] = *reinterpret_cast<const uint32_t*>(zh1 + c0 + 8);
            Ah[ks*4+3] = *reinterpret_cast<const uint32_t*>(zh2 + c0 + 8);
            Al[ks*4+0] = *reinterpret_cast<const uint32_t*>(zl1 + c0);
            Al[ks*4+1] = *reinterpret_cast<const uint32_t*>(zl2 + c0);
            Al[ks*4+2] = *reinterpret_cast<const uint32_t*>(zl1 + c0 + 8);
            Al[ks*4+3] = *reinterpret_cast<const uint32_t*>(zl2 + c0 + 8);
        }
    }

    // ---- B ldmatrix lane constants ----
    const int nl  = (lane & 7) | ((lane >> 4) << 3);
    const int h   = (lane >> 3) & 1;
    const int nl7 = nl & 7;

    // ---- cp.async prefetch mapping: thread -> (code row, 16B seg) ----
    const int prow = tid >> 3;        // 0..63
    const int pseg = tid & 7;         // 0..7
    const uint32_t pswz = (uint32_t)((pseg ^ (prow & 7)) << 4);
    auto prefetch = [&](int t, int buf) {
        int kt = t * NT;
        const __nv_bfloat16* gh = g_ehi + (size_t)(kt + prow) * DIM + pseg * 8;
        const __nv_bfloat16* gl = g_elo + (size_t)(kt + prow) * DIM + pseg * 8;
        uint32_t dbase = sb + SM_EB + buf * 65536 + prow * 128 + pswz;
        #pragma unroll
        for (int dcp = 0; dcp < 4; ++dcp) {
            cp_async16(dbase + dcp * 8192,         gh + dcp * 64);
            cp_async16(dbase + 32768 + dcp * 8192, gl + dcp * 64);
        }
        CP_COMMIT();
    };

    float acc[32];
    float bd = CUDART_INF_F; int bk = 0x7fffffff;
    float cd[MAXC]; int ck[MAXC]; int m = 0; int ovf = 0;
    float* Ds   = reinterpret_cast<float*>(smem + SM_D);
    float* en_s = reinterpret_cast<float*>(smem + SM_EN);

    prefetch(0, 0);

    #pragma unroll 1
    for (int t1 = 0; t1 < NTILES; ++t1) {
        if (t1 + 1 < NTILES) { prefetch(t1 + 1, (t1 + 1) & 1); CP_WAIT1(); }
        else                 { CP_WAIT0(); }
        __syncthreads();   // e tile t1 ready; also protects Ds vs prior scan

        if (tid < NT) en_s[tid] = g_enorm[t1 * NT + tid];

        #pragma unroll
        for (int i = 0; i < 32; ++i) acc[i] = 0.f;

        const uint32_t ebase = sb + SM_EB + (t1 & 1) * 65536;
        #pragma unroll
        for (int cc = 0; cc < 2; ++cc) {
            int dc = khalf * 2 + cc;
            uint32_t plane = ebase + dc * 8192 + nl * 128;
            #pragma unroll
            for (int ks = 0; ks < 4; ++ks) {
                int lk = cc * 4 + ks;
                uint32_t a0 = Ah[lk*4+0], a1 = Ah[lk*4+1],
                         a2 = Ah[lk*4+2], a3 = Ah[lk*4+3];
                uint32_t l0 = Al[lk*4+0], l1 = Al[lk*4+1],
                         l2 = Al[lk*4+2], l3 = Al[lk*4+3];
                uint32_t koff = (uint32_t)(((ks * 2 + h) ^ nl7) << 4);
                #pragma unroll
                for (int jj = 0; jj < 4; ++jj) {
                    uint32_t ba = plane + jj * 2048 + koff;
                    uint32_t bh0, bh1, bh2, bh3, bl0, bl1, bl2, bl3;
                    ldsm_x4(bh0, bh1, bh2, bh3, ba);
                    ldsm_x4(bl0, bl1, bl2, bl3, ba + 32768);
                    float* c0 = acc + (2*jj) * 4;
                    float* c1 = acc + (2*jj + 1) * 4;
                    mma_bf16(c0, a0, a1, a2, a3, bh0, bh1);
                    mma_bf16(c1, a0, a1, a2, a3, bh2, bh3);
                    mma_bf16(c0, a0, a1, a2, a3, bl0, bl1);
                    mma_bf16(c1, a0, a1, a2, a3, bl2, bl3);
                    mma_bf16(c0, l0, l1, l2, l3, bh0, bh1);
                    mma_bf16(c1, l0, l1, l2, l3, bh2, bh3);
                }
            }
        }

        // ---- dump partial D into this k-half's plane ----
        {
            float* Dp = Ds + khalf * (BM * DST);
            int r1 = mgrp * 16 + q, r2 = r1 + 8;
            #pragma unroll
            for (int j = 0; j < 8; ++j) {
                *reinterpret_cast<float2*>(&Dp[r1 * DST + j * 8 + 2 * e]) =
                    make_float2(acc[j*4+0], acc[j*4+1]);
                *reinterpret_cast<float2*>(&Dp[r2 * DST + j * 8 + 2 * e]) =
                    make_float2(acc[j*4+2], acc[j*4+3]);
            }
        }
        __syncthreads();

        // ---- per-point scan: sum both k-half planes, margin argmin ----
        if (tid < BM) {
            int kt = t1 * NT;
            const float* row0 = Ds + tid * DST;
            const float* row1 = Ds + BM * DST + tid * DST;
            #pragma unroll 4
            for (int i = 0; i < NT; ++i) {
                int c = (tid + i) & (NT - 1);
                float dap = fmaf(-2.0f, row0[c] + row1[c], en_s[c]);
                if (dap < bd + MARGIN) {
                    int k = kt + c;
                    float iv; int ik;
                    if (dap < bd) { iv = bd; ik = bk; bd = dap; bk = k; }
                    else          { iv = dap; ik = k; }
                    if (ik != 0x7fffffff) {
                        if (m == MAXC) {
                            int wv = 0;
                            for (int qq = 0; qq < MAXC; ++qq)
                                if (cd[qq] < bd + MARGIN) { cd[wv] = cd[qq]; ck[wv] = ck[qq]; ++wv; }
                            m = wv;
                        }
                        if (m < MAXC) { cd[m] = iv; ck[m] = ik; ++m; }
                        else ovf = 1;
                    }
                }
            }
        }
    }

    // ---- exact fp32 rescore of candidate set ----
    if (tid < BM) {
        int n = n0 + tid;
        const float* zr = z + (size_t)(n >> 10) * (DIM * HWSZ) + (n & 1023);
        float bestd = CUDART_INF_F; int bestk = 0x7fffffff;
        for (int ci = -1; ci < m; ++ci) {
            int k;
            if (ci < 0) k = bk;
            else {
                if (!(cd[ci] < bd + MARGIN)) continue;
                k = ck[ci];
                if (k == bk) continue;
            }
            const float* er = emb + (size_t)k * DIM;
            float dot = 0.f;
            #pragma unroll 8
            for (int c = 0; c < DIM; ++c)
                dot = fmaf(zr[(size_t)c * HWSZ], er[c], dot);
            float dd = fmaf(-2.0f, dot, g_enorm[k]);
            if (dd < bestd || (dd == bestd && k < bestk)) { bestd = dd; bestk = k; }
        }
        g_best_idx[n] = bestk;
        g_flag[n] = (unsigned)ovf;
    }
}

// ---------------- Kernel 1b: exact full-scan fallback for overflowed points ----------------
__global__ void k_fb(const float* __restrict__ z, const float* __restrict__ emb) {
    int w = (blockIdx.x * blockDim.x + threadIdx.x) >> 5;
    int lane = threadIdx.x & 31;
    if (w >= NPTS) return;
    if (g_flag[w] == 0) return;
    const float* zr = z + (size_t)(w >> 10) * (DIM * HWSZ) + (w & 1023);
    float bd = CUDART_INF_F; int bk = 0x7fffffff;
    for (int k = lane; k < NCODE; k += 32) {
        const float* er = emb + (size_t)k * DIM;
        float dot = 0.f;
        #pragma unroll 8
        for (int c = 0; c < DIM; ++c)
            dot = fmaf(zr[(size_t)c * HWSZ], er[c], dot);
    float dd = fmaf(-2.0f, dot, g_enorm[k]);
        if (dd < bd || (dd == bd && k < bk)) { bd = dd; bk = k; }
    }
    #pragma unroll
    for (int off = 16; off > 0; off >>= 1) {
        float od = __shfl_xor_sync(0xffffffffu, bd, off);
        int   ok = __shfl_xor_sync(0xffffffffu, bk, off);
        if (od < bd || (od == bd && ok < bk)) { bd = od; bk = ok; }
    }
    if (lane == 0) g_best_idx[w] = bk;
}

// ---------------- Kernel 2: output writer ----------------
__global__ void k_write(const float* __restrict__ z, const float* __restrict__ emb,
                        float* __restrict__ out, int out_size) {
    int i = blockIdx.x * 256 + threadIdx.x;
    if (i >= out_size) return;
    if (i < ZQ_ELEMS) {
        int hw = i & 1023;
        int bc = i >> 10;
        int c  = bc & 255;
        int b  = bc >> 8;
        int n  = (b << 10) + hw;
        int k  = g_best_idx[n];
        float ev = emb[(size_t)k * DIM + c];
        float zv = z[i];
        out[i] = __fadd_rn(zv, __fsub_rn(ev, zv));
    } else {
        int j = i - ZQ_ELEMS;
        out[i] = (j < NPTS) ? (float)g_best_idx[j] : 0.0f;
    }
}

extern "C" void kernel_launch(void* const* d_in, const int* in_sizes, int n_in,
                              void* d_out, int out_size) {
    const float* z   = (const float*)d_in[0];
    const float* emb = (const float*)d_in[1];
    if (in_sizes[0] != ZQ_ELEMS) {
        const float* tmp = z; z = emb; emb = tmp;
    }
    float* out = (float*)d_out;

    cudaFuncSetAttribute(k_vq, cudaFuncAttributeMaxDynamicSharedMemorySize,
                         SMEM_TOTAL);

    k_enorm<<<NCODE / 8, 256>>>(emb);
    k_esplit<<<(NCODE * DIM) / 256, 256>>>(emb);
    k_zsplit<<<2048, 256>>>(z);
    k_vq<<<NPTS / BM, 512, SMEM_TOTAL>>>(z, emb);
    k_fb<<<NPTS / 8, 256>>>(z, emb);
    int wgrid = (out_size + 255) / 256;
    k_write<<<wgrid, 256>>>(z, emb, out, out_size);
}